// round 2
// baseline (speedup 1.0000x reference)
#include <cuda_runtime.h>

#define LN_EPS 1e-5f

// ---------------- geometry ----------------
constexpr int TM   = 32;           // rows per CTA
constexpr int KC   = 16;           // K chunk for weight streaming
constexpr int WSLD = KC + 4;       // 20 floats, padded (bank-conflict free)
constexpr int LDX  = 776;          // layer-1 input stride (768 used), 776%32=8
constexpr int LDH  = 520;          // hidden stride (512/128 used), 520%32=8

// smem float offsets
constexpr int XS_OFF = 0;                       // 32*776 = 24832 (X tile, later h2)
constexpr int HS_OFF = TM * LDX;                // 32*520 = 16640 (h1, later h3)
constexpr int WS_OFF = HS_OFF + TM * LDH;       // 512*20 = 10240 (weight chunk)
constexpr int SMEM_FLOATS = WS_OFF + 512 * WSLD;  // 51712 floats
constexpr int SMEM_BYTES  = SMEM_FLOATS * 4;      // 206848 B

// ---------------- scratch (no runtime alloc allowed) ----------------
__device__ float g_zs[32768 * 32];
__device__ float g_zq[65536 * 32];
__device__ float g_psum[64 * 32];
__device__ float g_pcnt[64];

// ---------------- fused backbone ----------------
// GEMM: out[TM][DOUT] = in[TM][DIN] @ W^T + bias, W global row-major [DOUT][DIN].
// 8 warps; warp w owns cols [w*CPW, (w+1)*CPW). Per-thread 8 rows x CPT cols.
template <int DIN, int DOUT, int LDI, int LDO>
__device__ __forceinline__ void gemm_tile(const float* __restrict__ in_s,
                                          const float* __restrict__ Wg,
                                          const float* __restrict__ bias,
                                          float* __restrict__ out_s,
                                          float* __restrict__ ws, int tid) {
    constexpr int CPW = DOUT / 8;     // cols per warp (64 / 64 / 16)
    constexpr int CPT = CPW / 8;      // cols per thread (8 / 8 / 2)
    const int lane = tid & 31;
    const int warp = tid >> 5;
    const int rg   = lane >> 3;       // row group 0..3  (rows = rg + 4*i)
    const int cg   = lane & 7;        // col group 0..7  (cols = base + 8*j)
    const int cbase = warp * CPW + cg;

    float acc[8][CPT];
#pragma unroll
    for (int i = 0; i < 8; i++)
#pragma unroll
        for (int j = 0; j < CPT; j++) acc[i][j] = 0.f;

    for (int k0 = 0; k0 < DIN; k0 += KC) {
        // stage W chunk [DOUT][KC] -> ws (stride WSLD)
        constexpr int NV = DOUT * KC / 4 / 256;   // float4 per thread (8 / 8 / 2)
#pragma unroll
        for (int i = 0; i < NV; i++) {
            int idx = tid + i * 256;
            int nc = idx >> 2;
            int kq = idx & 3;
            float4 v = *(const float4*)&Wg[(size_t)nc * DIN + k0 + kq * 4];
            *(float4*)&ws[nc * WSLD + kq * 4] = v;
        }
        __syncthreads();
#pragma unroll
        for (int kk = 0; kk < KC; kk += 4) {
            float4 a[8], b[CPT];
#pragma unroll
            for (int i = 0; i < 8; i++)
                a[i] = *(const float4*)&in_s[(rg + 4 * i) * LDI + k0 + kk];
#pragma unroll
            for (int j = 0; j < CPT; j++)
                b[j] = *(const float4*)&ws[(cbase + 8 * j) * WSLD + kk];
#pragma unroll
            for (int i = 0; i < 8; i++)
#pragma unroll
                for (int j = 0; j < CPT; j++) {
                    acc[i][j] = fmaf(a[i].x, b[j].x, acc[i][j]);
                    acc[i][j] = fmaf(a[i].y, b[j].y, acc[i][j]);
                    acc[i][j] = fmaf(a[i].z, b[j].z, acc[i][j]);
                    acc[i][j] = fmaf(a[i].w, b[j].w, acc[i][j]);
                }
        }
        __syncthreads();
    }
    // epilogue: +bias, store to smem
#pragma unroll
    for (int j = 0; j < CPT; j++) {
        int c = cbase + 8 * j;
        float bb = __ldg(&bias[c]);
#pragma unroll
        for (int i = 0; i < 8; i++) {
            int r = rg + 4 * i;
            out_s[r * LDO + c] = acc[i][j] + bb;
        }
    }
}

template <int DOUT, int LDO>
__device__ __forceinline__ void ln_relu(float* __restrict__ h,
                                        const float* __restrict__ g,
                                        const float* __restrict__ be, int tid) {
    const int lane = tid & 31;
    const int warp = tid >> 5;
#pragma unroll
    for (int r = 0; r < 4; r++) {
        int row = warp * 4 + r;
        float* hr = h + row * LDO;
        float s = 0.f, s2 = 0.f;
#pragma unroll
        for (int c = lane; c < DOUT; c += 32) {
            float v = hr[c];
            s += v;
            s2 += v * v;
        }
#pragma unroll
        for (int o = 16; o > 0; o >>= 1) {
            s  += __shfl_xor_sync(0xffffffff, s, o);
            s2 += __shfl_xor_sync(0xffffffff, s2, o);
        }
        float mu  = s * (1.0f / DOUT);
        float var = s2 * (1.0f / DOUT) - mu * mu;
        float rs  = rsqrtf(var + LN_EPS);
#pragma unroll
        for (int c = lane; c < DOUT; c += 32) {
            float v = (hr[c] - mu) * rs * __ldg(&g[c]) + __ldg(&be[c]);
            hr[c] = fmaxf(v, 0.f);
        }
    }
}

__global__ __launch_bounds__(256, 1) void backbone_kernel(
    const float* __restrict__ X, float* __restrict__ Z,
    const float* __restrict__ W1, const float* __restrict__ b1,
    const float* __restrict__ g1, const float* __restrict__ be1,
    const float* __restrict__ W2, const float* __restrict__ b2,
    const float* __restrict__ g2, const float* __restrict__ be2,
    const float* __restrict__ W3, const float* __restrict__ b3,
    const float* __restrict__ g3, const float* __restrict__ be3,
    const float* __restrict__ W4, const float* __restrict__ b4) {
    extern __shared__ float smem[];
    float* xs = smem + XS_OFF;
    float* hs = smem + HS_OFF;
    float* ws = smem + WS_OFF;
    const int tid = threadIdx.x;
    const int r0  = blockIdx.x * TM;

    // stage X tile [32][768] -> xs (stride 776)
    const float4* Xg = (const float4*)(X + (size_t)r0 * 768);
#pragma unroll
    for (int i = 0; i < 24; i++) {
        int idx = tid + i * 256;        // 0..6143 float4s
        int row = idx / 192;
        int kq  = idx % 192;
        float4 v = Xg[row * 192 + kq];
        *(float4*)&xs[row * LDX + kq * 4] = v;
    }
    __syncthreads();

    gemm_tile<768, 512, LDX, LDH>(xs, W1, b1, hs, ws, tid);
    __syncthreads();
    ln_relu<512, LDH>(hs, g1, be1, tid);
    __syncthreads();

    gemm_tile<512, 512, LDH, LDH>(hs, W2, b2, xs, ws, tid);
    __syncthreads();
    ln_relu<512, LDH>(xs, g2, be2, tid);
    __syncthreads();

    gemm_tile<512, 128, LDH, LDH>(xs, W3, b3, hs, ws, tid);
    __syncthreads();
    ln_relu<128, LDH>(hs, g3, be3, tid);
    __syncthreads();

    // layer 4: [32][32] = h3[32][128] @ W4^T + b4  -> global Z
    // stage W4 [32][128] -> ws (stride 132)
#pragma unroll
    for (int i = 0; i < 4; i++) {
        int idx = tid + i * 256;        // 0..1023 float4s
        int n = idx >> 5;
        int kq = idx & 31;
        float4 v = *(const float4*)&W4[n * 128 + kq * 4];
        *(float4*)&ws[n * 132 + kq * 4] = v;
    }
    __syncthreads();
#pragma unroll
    for (int p = 0; p < 4; p++) {
        int m = p * 8 + (tid >> 5);
        int n = tid & 31;
        float acc = 0.f;
#pragma unroll
        for (int k = 0; k < 128; k += 4) {
            float4 a = *(const float4*)&hs[m * LDH + k];
            float4 b = *(const float4*)&ws[n * 132 + k];
            acc = fmaf(a.x, b.x, acc);
            acc = fmaf(a.y, b.y, acc);
            acc = fmaf(a.z, b.z, acc);
            acc = fmaf(a.w, b.w, acc);
        }
        Z[(size_t)(r0 + m) * 32 + n] = acc + __ldg(&b4[n]);
    }
}

// ---------------- prototypes ----------------
__global__ void zero_proto_kernel() {
    int t = blockIdx.x * blockDim.x + threadIdx.x;
    if (t < 64 * 32) g_psum[t] = 0.f;
    if (t < 64) g_pcnt[t] = 0.f;
}

// labels are int32: JAX default config has x64 disabled, so the reference's
// jnp.int64 silently becomes int32 in the dataset. (Reading as int64 was the
// R1 illegal-access bug.)
__global__ void proto_accum_kernel(const int* __restrict__ labels) {
    __shared__ float ssum[64 * 32];
    __shared__ float scnt[64];
    int tid = threadIdx.x, lane = tid & 31, warp = tid >> 5;
    for (int t = tid; t < 64 * 32; t += 256) ssum[t] = 0.f;
    if (tid < 64) scnt[tid] = 0.f;
    __syncthreads();
    int rbase = blockIdx.x * 512;
    for (int r = rbase + warp; r < rbase + 512; r += 8) {
        int lab = labels[r];
        lab = max(0, min(63, lab));   // free safety: degrade to rel_err, not crash
        float v = g_zs[(size_t)r * 32 + lane];
        atomicAdd(&ssum[lab * 32 + lane], v);
        if (lane == 0) atomicAdd(&scnt[lab], 1.f);
    }
    __syncthreads();
    for (int t = tid; t < 64 * 32; t += 256) atomicAdd(&g_psum[t], ssum[t]);
    if (tid < 64) atomicAdd(&g_pcnt[tid], scnt[tid]);
}

__global__ void proto_finalize_kernel() {
    int tid = threadIdx.x;
    for (int i = tid; i < 64 * 32; i += 256) {
        int c = i >> 5;
        g_psum[i] = g_psum[i] / fmaxf(g_pcnt[c], 1.f);
    }
}

// ---------------- -cdist ----------------
__global__ __launch_bounds__(256) void dist_kernel(float* __restrict__ out) {
    __shared__ float ps[64 * 33];
    __shared__ float pn[64];
    __shared__ float qs[16 * 33];
    int tid = threadIdx.x;
    for (int i = tid; i < 64 * 32; i += 256)
        ps[(i >> 5) * 33 + (i & 31)] = g_psum[i];
    int qbase = blockIdx.x * 16;
    for (int i = tid; i < 16 * 32; i += 256) {
        int q = i >> 5, k = i & 31;
        qs[q * 33 + k] = g_zq[(size_t)(qbase + q) * 32 + k];
    }
    __syncthreads();
    if (tid < 64) {
        float s = 0.f;
#pragma unroll
        for (int k = 0; k < 32; k++) {
            float v = ps[tid * 33 + k];
            s += v * v;
        }
        pn[tid] = s;
    }
    __syncthreads();
    int c = tid & 63;
#pragma unroll
    for (int p = 0; p < 4; p++) {
        int q = p * 4 + (tid >> 6);
        float dot = 0.f, qn = 0.f;
#pragma unroll
        for (int k = 0; k < 32; k++) {
            float a = qs[q * 33 + k];
            float b = ps[c * 33 + k];
            dot = fmaf(a, b, dot);
            qn  = fmaf(a, a, qn);
        }
        float sq = qn + pn[c] - 2.f * dot;
        out[(size_t)(qbase + q) * 64 + c] = -sqrtf(fmaxf(sq, 0.f));
    }
}

// ---------------- launch ----------------
extern "C" void kernel_launch(void* const* d_in, const int* in_sizes, int n_in,
                              void* d_out, int out_size) {
    const float* sup = (const float*)d_in[0];
    const int*   lab = (const int*)d_in[1];
    const float* qry = (const float*)d_in[2];
    const float* W1 = (const float*)d_in[3];
    const float* b1 = (const float*)d_in[4];
    const float* g1 = (const float*)d_in[5];
    const float* be1 = (const float*)d_in[6];
    const float* W2 = (const float*)d_in[7];
    const float* b2 = (const float*)d_in[8];
    const float* g2 = (const float*)d_in[9];
    const float* be2 = (const float*)d_in[10];
    const float* W3 = (const float*)d_in[11];
    const float* b3 = (const float*)d_in[12];
    const float* g3 = (const float*)d_in[13];
    const float* be3 = (const float*)d_in[14];
    const float* W4 = (const float*)d_in[15];
    const float* b4 = (const float*)d_in[16];

    cudaFuncSetAttribute(backbone_kernel,
                         cudaFuncAttributeMaxDynamicSharedMemorySize, SMEM_BYTES);

    float* zs_ptr = nullptr;
    float* zq_ptr = nullptr;
    cudaGetSymbolAddress((void**)&zs_ptr, g_zs);
    cudaGetSymbolAddress((void**)&zq_ptr, g_zq);

    backbone_kernel<<<32768 / TM, 256, SMEM_BYTES>>>(
        sup, zs_ptr, W1, b1, g1, be1, W2, b2, g2, be2, W3, b3, g3, be3, W4, b4);
    backbone_kernel<<<65536 / TM, 256, SMEM_BYTES>>>(
        qry, zq_ptr, W1, b1, g1, be1, W2, b2, g2, be2, W3, b3, g3, be3, W4, b4);
    zero_proto_kernel<<<8, 256>>>();
    proto_accum_kernel<<<64, 256>>>(lab);
    proto_finalize_kernel<<<1, 256>>>();
    dist_kernel<<<65536 / 16, 256>>>((float*)d_out);
}

// round 5
// speedup vs baseline: 1.3304x; 1.3304x over previous
#include <cuda_runtime.h>
#include <cuda_bf16.h>
#include <cstdint>

#define LN_EPS 1e-5f

// ============================ PTX helpers ============================
__device__ __forceinline__ uint32_t smem_u32(const void* p) {
    uint32_t a;
    asm("{ .reg .u64 t; cvta.to.shared.u64 t, %1; cvt.u32.u64 %0, t; }"
        : "=r"(a) : "l"(p));
    return a;
}

#define LDSM4(r, addr)                                                        \
    asm volatile(                                                             \
        "ldmatrix.sync.aligned.m8n8.x4.shared.b16 {%0,%1,%2,%3}, [%4];"       \
        : "=r"((r)[0]), "=r"((r)[1]), "=r"((r)[2]), "=r"((r)[3])              \
        : "r"(addr))

#define MMA16816(d, a, b0, b1)                                                \
    asm volatile(                                                             \
        "mma.sync.aligned.m16n8k16.row.col.f32.bf16.bf16.f32 "                \
        "{%0,%1,%2,%3}, {%4,%5,%6,%7}, {%8,%9}, {%0,%1,%2,%3};"               \
        : "+f"((d)[0]), "+f"((d)[1]), "+f"((d)[2]), "+f"((d)[3])              \
        : "r"((a)[0]), "r"((a)[1]), "r"((a)[2]), "r"((a)[3]),                 \
          "r"(b0), "r"(b1))

#define CP_ASYNC16(dst, src)                                                  \
    asm volatile("cp.async.cg.shared.global [%0], [%1], 16;"                  \
                 :: "r"(dst), "l"(src))
#define CP_ASYNC_COMMIT() asm volatile("cp.async.commit_group;" ::: "memory")
#define CP_ASYNC_WAIT0()  asm volatile("cp.async.wait_group 0;" ::: "memory")

// ============================ geometry ============================
constexpr int LDTB = 144;   // smem tile row stride in bytes (conflict-free)
constexpr int TILE = 128 * LDTB;     // 18432 B per [128 x 64] bf16 tile
// A splits a0,a1,a2 then W splits w0,w1,w2
constexpr int SM_A0 = 0;
constexpr int SM_W0 = 3 * TILE;                 // 55296
constexpr int SM_BIAS = 6 * TILE;               // 110592, 512 f32
constexpr int SM_GIN  = SM_BIAS + 2048;         // 112640, 768 f32
constexpr int SM_BEIN = SM_GIN + 3072;          // 115712
constexpr int SM_S1   = SM_BEIN + 3072;         // 118784, 128 f32
constexpr int SM_S2   = SM_S1 + 512;            // 119296
constexpr int SM_TOTAL = SM_S2 + 512;           // 119808 B

constexpr int TM  = 128;
constexpr int KCH = 64;

// ============================ scratch ============================
__device__ float  g_h0[98304ull * 512];
__device__ float  g_h1[98304ull * 512];
__device__ float2 g_stats_a[98304];
__device__ float2 g_stats_b[98304];
__device__ float  g_psum[64 * 32];
__device__ float  g_pcnt[64];
// pre-split weights (row-major bf16 per layer, concatenated)
// offsets: L1=0 (768*512), L2=393216 (512*512), L3=655360 (512*128),
//          L4=720896 (128*32), total 724992
__device__ __nv_bfloat16 g_w0[724992];
__device__ __nv_bfloat16 g_w1[724992];
__device__ __nv_bfloat16 g_w2[724992];

// ============================ 3-way split ============================
__device__ __forceinline__ void split3(float a, __nv_bfloat16& h0,
                                       __nv_bfloat16& h1, __nv_bfloat16& h2) {
    h0 = __float2bfloat16_rn(a);
    float r = a - __bfloat162float(h0);
    h1 = __float2bfloat16_rn(r);
    float r2 = r - __bfloat162float(h1);
    h2 = __float2bfloat16_rn(r2);
}

__device__ __forceinline__ uint32_t pack2(__nv_bfloat16 a, __nv_bfloat16 b) {
    return ((uint32_t)__bfloat16_as_ushort(b) << 16) |
           (uint32_t)__bfloat16_as_ushort(a);
}

// split 8 fp32 into three bf16 tiles at fixed TILE deltas
__device__ __forceinline__ void split3_store8(const float* x, char* sm,
                                              uint32_t so) {
    __nv_bfloat16 h0[8], h1[8], h2[8];
#pragma unroll
    for (int j = 0; j < 8; j++) split3(x[j], h0[j], h1[j], h2[j]);
    uint4 U0 = make_uint4(pack2(h0[0], h0[1]), pack2(h0[2], h0[3]),
                          pack2(h0[4], h0[5]), pack2(h0[6], h0[7]));
    uint4 U1 = make_uint4(pack2(h1[0], h1[1]), pack2(h1[2], h1[3]),
                          pack2(h1[4], h1[5]), pack2(h1[6], h1[7]));
    uint4 U2 = make_uint4(pack2(h2[0], h2[1]), pack2(h2[2], h2[3]),
                          pack2(h2[4], h2[5]), pack2(h2[6], h2[7]));
    *(uint4*)(sm + SM_A0 + so) = U0;
    *(uint4*)(sm + SM_A0 + TILE + so) = U1;
    *(uint4*)(sm + SM_A0 + 2 * TILE + so) = U2;
}

// ============================ W prep kernel ============================
__global__ void split_w_kernel(const float* __restrict__ W, int off, int n) {
    int i = blockIdx.x * 256 + threadIdx.x;
    if (i < n) {
        __nv_bfloat16 h0, h1, h2;
        split3(W[i], h0, h1, h2);
        g_w0[off + i] = h0;
        g_w1[off + i] = h1;
        g_w2[off + i] = h2;
    }
}

// ============================ layer kernel ============================
template <int DIN, int DOUT, bool NORM_IN, bool LN_OUT>
__global__ __launch_bounds__(256, 1) void layer_kernel(
    const float*  __restrict__ A,
    const float2* __restrict__ stats_in,
    const float*  __restrict__ gin,
    const float*  __restrict__ bein,
    int w_off,                          // offset into g_w* for this layer
    const float*  __restrict__ bias,
    float*        __restrict__ out,
    float2*       __restrict__ stats_out) {
    extern __shared__ char sm[];
    const uint32_t smb = smem_u32(sm);
    const int tid  = threadIdx.x;
    const int lane = tid & 31;
    const int wid  = tid >> 5;
    const int wr   = wid >> 1;
    const int wc   = wid & 1;
    const int64_t r0 = (int64_t)blockIdx.x * TM;

    constexpr int NPASS = (DOUT > 128) ? 128 : DOUT;
    constexpr int NT    = DOUT / NPASS;
    constexpr int WC    = NPASS / 2;
    constexpr int NFRAG = WC / 8;
    constexpr int NCH   = DIN / KCH;

    const int R0  = wr * 32;
    const int C0w = wc * WC;

    const int sub  = lane >> 3;
    const int arow = (sub & 1) * 8 + (lane & 7);
    const int acol = (sub >> 1) * 8;
    const int brow = (sub >> 1) * 8 + (lane & 7);
    const int bcol = (sub & 1) * 8;

    float* bias_s = (float*)(sm + SM_BIAS);
    float* gin_s  = (float*)(sm + SM_GIN);
    float* bein_s = (float*)(sm + SM_BEIN);
    float* s1_s   = (float*)(sm + SM_S1);
    float* s2_s   = (float*)(sm + SM_S2);

    for (int i = tid; i < DOUT; i += 256) bias_s[i] = bias[i];
    if (NORM_IN)
        for (int i = tid; i < DIN; i += 256) {
            gin_s[i]  = gin[i];
            bein_s[i] = bein[i];
        }
    if (LN_OUT && tid < TM) {
        s1_s[tid] = 0.f;
        s2_s[tid] = 0.f;
    }

    const __nv_bfloat16* wsp[3] = {g_w0 + w_off, g_w1 + w_off, g_w2 + w_off};

    for (int nt = 0; nt < NT; nt++) {
        float acc[2][NFRAG][4];
#pragma unroll
        for (int i = 0; i < 2; i++)
#pragma unroll
            for (int j = 0; j < NFRAG; j++)
#pragma unroll
                for (int q = 0; q < 4; q++) acc[i][j][q] = 0.f;

        const int n0 = nt * NPASS;
        for (int ch = 0; ch < NCH; ch++) {
            const int k0 = ch * KCH;
            __syncthreads();   // previous tile reads complete

            // ---- W copy via cp.async: 3 splits x NPASS rows x 8 quads ----
            for (int i = tid; i < NPASS * 24; i += 256) {
                int s = i / (NPASS * 8);
                int rem = i - s * NPASS * 8;
                int r = rem >> 3, q = rem & 7;
                const __nv_bfloat16* src =
                    wsp[s] + (int64_t)(n0 + r) * DIN + k0 + q * 8;
                uint32_t dst = smb + SM_W0 + s * TILE +
                               (uint32_t)(r * LDTB + q * 16);
                CP_ASYNC16(dst, src);
            }
            CP_ASYNC_COMMIT();

            // ---- A convert (overlaps with async W copy) ----
            for (int i = tid; i < TM * 8; i += 256) {
                int r = i >> 3, q = i & 7;
                const float* s = A + (r0 + r) * (int64_t)DIN + k0 + q * 8;
                float4 v0 = *(const float4*)s;
                float4 v1 = *(const float4*)(s + 4);
                float x[8] = {v0.x, v0.y, v0.z, v0.w, v1.x, v1.y, v1.z, v1.w};
                if (NORM_IN) {
                    float2 st = stats_in[r0 + r];
#pragma unroll
                    for (int j = 0; j < 8; j++) {
                        int c = k0 + q * 8 + j;
                        x[j] = fmaxf((x[j] - st.x) * st.y * gin_s[c] + bein_s[c],
                                     0.f);
                    }
                }
                split3_store8(x, sm, (uint32_t)(r * LDTB + q * 16));
            }
            CP_ASYNC_WAIT0();
            __syncthreads();

            // ---- MMA: 6 products over 4 k16 steps ----
#pragma unroll
            for (int kk = 0; kk < KCH; kk += 16) {
                uint32_t af[3][2][4];
#pragma unroll
                for (int s = 0; s < 3; s++)
#pragma unroll
                    for (int i = 0; i < 2; i++) {
                        uint32_t ad = smb + SM_A0 + s * TILE +
                                      (uint32_t)((R0 + i * 16 + arow) * LDTB +
                                                 (kk + acol) * 2);
                        LDSM4(af[s][i], ad);
                    }
#pragma unroll
                for (int j2 = 0; j2 < NFRAG / 2; j2++) {
                    uint32_t bf_[3][4];
#pragma unroll
                    for (int t = 0; t < 3; t++) {
                        uint32_t bd = smb + SM_W0 + t * TILE +
                                      (uint32_t)((C0w + j2 * 16 + brow) * LDTB +
                                                 (kk + bcol) * 2);
                        LDSM4(bf_[t], bd);
                    }
                    // products (a_s, w_t): small terms first
                    constexpr int PS[6] = {2, 0, 1, 1, 0, 0};
                    constexpr int PT[6] = {0, 2, 1, 0, 1, 0};
#pragma unroll
                    for (int p = 0; p < 6; p++) {
                        const int s = PS[p], t = PT[p];
#pragma unroll
                        for (int i = 0; i < 2; i++) {
                            MMA16816(acc[i][2 * j2],     af[s][i],
                                     bf_[t][0], bf_[t][1]);
                            MMA16816(acc[i][2 * j2 + 1], af[s][i],
                                     bf_[t][2], bf_[t][3]);
                        }
                    }
                }
            }
        }

        // ---- epilogue: bias, store pre-LN, accumulate LN stats ----
#pragma unroll
        for (int i = 0; i < 2; i++) {
            const int rla = R0 + i * 16 + (lane >> 2);
            float s1a = 0.f, s2a = 0.f, s1b = 0.f, s2b = 0.f;
#pragma unroll
            for (int j = 0; j < NFRAG; j++) {
                int cg = n0 + C0w + j * 8 + (lane & 3) * 2;
                float v0 = acc[i][j][0] + bias_s[cg];
                float v1 = acc[i][j][1] + bias_s[cg + 1];
                float v2 = acc[i][j][2] + bias_s[cg];
                float v3 = acc[i][j][3] + bias_s[cg + 1];
                *(float2*)(out + (r0 + rla) * (int64_t)DOUT + cg) =
                    make_float2(v0, v1);
                *(float2*)(out + (r0 + rla + 8) * (int64_t)DOUT + cg) =
                    make_float2(v2, v3);
                if (LN_OUT) {
                    s1a += v0 + v1; s2a += fmaf(v0, v0, v1 * v1);
                    s1b += v2 + v3; s2b += fmaf(v2, v2, v3 * v3);
                }
            }
            if (LN_OUT) {
#pragma unroll
                for (int o = 1; o <= 2; o <<= 1) {
                    s1a += __shfl_xor_sync(0xffffffffu, s1a, o);
                    s2a += __shfl_xor_sync(0xffffffffu, s2a, o);
                    s1b += __shfl_xor_sync(0xffffffffu, s1b, o);
                    s2b += __shfl_xor_sync(0xffffffffu, s2b, o);
                }
                if ((lane & 3) == 0) {
                    atomicAdd(&s1_s[rla], s1a);
                    atomicAdd(&s2_s[rla], s2a);
                    atomicAdd(&s1_s[rla + 8], s1b);
                    atomicAdd(&s2_s[rla + 8], s2b);
                }
            }
        }
    }

    if (LN_OUT) {
        __syncthreads();
        if (tid < TM) {
            float mu  = s1_s[tid] * (1.0f / DOUT);
            float var = s2_s[tid] * (1.0f / DOUT) - mu * mu;
            stats_out[r0 + tid] = make_float2(mu, rsqrtf(var + LN_EPS));
        }
    }
}

// ============================ prototypes ============================
__global__ void zero_proto_kernel() {
    int t = blockIdx.x * blockDim.x + threadIdx.x;
    if (t < 64 * 32) g_psum[t] = 0.f;
    if (t < 64) g_pcnt[t] = 0.f;
}

__global__ void proto_accum_kernel(const int* __restrict__ labels,
                                   const float* __restrict__ zs) {
    __shared__ float ssum[64 * 32];
    __shared__ float scnt[64];
    int tid = threadIdx.x, lane = tid & 31, warp = tid >> 5;
    for (int t = tid; t < 64 * 32; t += 256) ssum[t] = 0.f;
    if (tid < 64) scnt[tid] = 0.f;
    __syncthreads();
    int rbase = blockIdx.x * 512;
    for (int r = rbase + warp; r < rbase + 512; r += 8) {
        int lab = labels[r];
        lab = max(0, min(63, lab));
        float v = zs[(size_t)r * 32 + lane];
        atomicAdd(&ssum[lab * 32 + lane], v);
        if (lane == 0) atomicAdd(&scnt[lab], 1.f);
    }
    __syncthreads();
    for (int t = tid; t < 64 * 32; t += 256) atomicAdd(&g_psum[t], ssum[t]);
    if (tid < 64) atomicAdd(&g_pcnt[tid], scnt[tid]);
}

__global__ void proto_finalize_kernel() {
    int tid = threadIdx.x;
    for (int i = tid; i < 64 * 32; i += 256) {
        int c = i >> 5;
        g_psum[i] = g_psum[i] / fmaxf(g_pcnt[c], 1.f);
    }
}

// ============================ -cdist ============================
__global__ __launch_bounds__(256) void dist_kernel(const float* __restrict__ zq,
                                                   float* __restrict__ out) {
    __shared__ float ps[64 * 33];
    __shared__ float pn[64];
    __shared__ float qs[16 * 33];
    int tid = threadIdx.x;
    for (int i = tid; i < 64 * 32; i += 256)
        ps[(i >> 5) * 33 + (i & 31)] = g_psum[i];
    int qbase = blockIdx.x * 16;
    for (int i = tid; i < 16 * 32; i += 256) {
        int q = i >> 5, k = i & 31;
        qs[q * 33 + k] = zq[(size_t)(qbase + q) * 32 + k];
    }
    __syncthreads();
    if (tid < 64) {
        float s = 0.f;
#pragma unroll
        for (int k = 0; k < 32; k++) {
            float v = ps[tid * 33 + k];
            s += v * v;
        }
        pn[tid] = s;
    }
    __syncthreads();
    int c = tid & 63;
#pragma unroll
    for (int p = 0; p < 4; p++) {
        int q = p * 4 + (tid >> 6);
        float dot = 0.f, qn = 0.f;
#pragma unroll
        for (int k = 0; k < 32; k++) {
            float a = qs[q * 33 + k];
            float b = ps[c * 33 + k];
            dot = fmaf(a, b, dot);
            qn  = fmaf(a, a, qn);
        }
        float sq = qn + pn[c] - 2.f * dot;
        out[(size_t)(qbase + q) * 64 + c] = -sqrtf(fmaxf(sq, 0.f));
    }
}

// ============================ launch ============================
extern "C" void kernel_launch(void* const* d_in, const int* in_sizes, int n_in,
                              void* d_out, int out_size) {
    const float* sup = (const float*)d_in[0];
    const int*   lab = (const int*)d_in[1];
    const float* qry = (const float*)d_in[2];
    const float* W1 = (const float*)d_in[3];
    const float* b1 = (const float*)d_in[4];
    const float* g1 = (const float*)d_in[5];
    const float* be1 = (const float*)d_in[6];
    const float* W2 = (const float*)d_in[7];
    const float* b2 = (const float*)d_in[8];
    const float* g2 = (const float*)d_in[9];
    const float* be2 = (const float*)d_in[10];
    const float* W3 = (const float*)d_in[11];
    const float* b3 = (const float*)d_in[12];
    const float* g3 = (const float*)d_in[13];
    const float* be3 = (const float*)d_in[14];
    const float* W4 = (const float*)d_in[15];
    const float* b4 = (const float*)d_in[16];

    cudaFuncSetAttribute(layer_kernel<768, 512, false, true>,
                         cudaFuncAttributeMaxDynamicSharedMemorySize, SM_TOTAL);
    cudaFuncSetAttribute(layer_kernel<512, 512, true, true>,
                         cudaFuncAttributeMaxDynamicSharedMemorySize, SM_TOTAL);
    cudaFuncSetAttribute(layer_kernel<512, 128, true, true>,
                         cudaFuncAttributeMaxDynamicSharedMemorySize, SM_TOTAL);
    cudaFuncSetAttribute(layer_kernel<128, 32, true, false>,
                         cudaFuncAttributeMaxDynamicSharedMemorySize, SM_TOTAL);

    float*  h0 = nullptr;
    float*  h1 = nullptr;
    float2* sa = nullptr;
    float2* sb = nullptr;
    cudaGetSymbolAddress((void**)&h0, g_h0);
    cudaGetSymbolAddress((void**)&h1, g_h1);
    cudaGetSymbolAddress((void**)&sa, g_stats_a);
    cudaGetSymbolAddress((void**)&sb, g_stats_b);

    // weight pre-split (layer offsets: 0, 393216, 655360, 720896)
    split_w_kernel<<<(393216 + 255) / 256, 256>>>(W1, 0, 393216);
    split_w_kernel<<<(262144 + 255) / 256, 256>>>(W2, 393216, 262144);
    split_w_kernel<<<(65536 + 255) / 256, 256>>>(W3, 655360, 65536);
    split_w_kernel<<<(4096 + 255) / 256, 256>>>(W4, 720896, 4096);

    // L1: raw input -> pre-LN h + stats_a
    layer_kernel<768, 512, false, true><<<256, 256, SM_TOTAL>>>(
        sup, nullptr, nullptr, nullptr, 0, b1, h0, sa);
    layer_kernel<768, 512, false, true><<<512, 256, SM_TOTAL>>>(
        qry, nullptr, nullptr, nullptr, 0, b1,
        h0 + (size_t)32768 * 512, sa + 32768);
    // L2
    layer_kernel<512, 512, true, true><<<768, 256, SM_TOTAL>>>(
        h0, sa, g1, be1, 393216, b2, h1, sb);
    // L3
    layer_kernel<512, 128, true, true><<<768, 256, SM_TOTAL>>>(
        h1, sb, g2, be2, 655360, b3, h0, sa);
    // L4 -> z
    layer_kernel<128, 32, true, false><<<768, 256, SM_TOTAL>>>(
        h0, sa, g3, be3, 720896, b4, h1, nullptr);

    zero_proto_kernel<<<8, 256>>>();
    proto_accum_kernel<<<64, 256>>>(lab, h1);
    proto_finalize_kernel<<<1, 256>>>();
    dist_kernel<<<65536 / 16, 256>>>(h1 + (size_t)32768 * 32, (float*)d_out);
}

// round 6
// speedup vs baseline: 1.8124x; 1.3623x over previous
#include <cuda_runtime.h>
#include <cuda_bf16.h>
#include <cstdint>

#define LN_EPS 1e-5f

// ============================ PTX helpers ============================
__device__ __forceinline__ uint32_t smem_u32(const void* p) {
    uint32_t a;
    asm("{ .reg .u64 t; cvta.to.shared.u64 t, %1; cvt.u32.u64 %0, t; }"
        : "=r"(a) : "l"(p));
    return a;
}

__device__ __forceinline__ uint32_t swz(uint32_t off) {
    return off ^ ((off >> 3) & 0x70);   // SW128: XOR 16B-unit idx with row&7
}

#define LDSM4(r, addr)                                                        \
    asm volatile(                                                             \
        "ldmatrix.sync.aligned.m8n8.x4.shared.b16 {%0,%1,%2,%3}, [%4];"       \
        : "=r"((r)[0]), "=r"((r)[1]), "=r"((r)[2]), "=r"((r)[3])              \
        : "r"(addr))

#define MMA16816(d, a, b0, b1)                                                \
    asm volatile(                                                             \
        "mma.sync.aligned.m16n8k16.row.col.f32.bf16.bf16.f32 "                \
        "{%0,%1,%2,%3}, {%4,%5,%6,%7}, {%8,%9}, {%0,%1,%2,%3};"               \
        : "+f"((d)[0]), "+f"((d)[1]), "+f"((d)[2]), "+f"((d)[3])              \
        : "r"((a)[0]), "r"((a)[1]), "r"((a)[2]), "r"((a)[3]),                 \
          "r"(b0), "r"(b1))

#define CP_ASYNC16(dst, src)                                                  \
    asm volatile("cp.async.cg.shared.global [%0], [%1], 16;"                  \
                 :: "r"(dst), "l"(src))
#define CP_ASYNC_COMMIT() asm volatile("cp.async.commit_group;" ::: "memory")
#define CP_ASYNC_WAIT1()  asm volatile("cp.async.wait_group 1;" ::: "memory")
#define CP_ASYNC_WAIT0()  asm volatile("cp.async.wait_group 0;" ::: "memory")

// ============================ geometry ============================
constexpr int KCH   = 64;                 // K elems per chunk (128 B bf16 rows)
constexpr int TILEB = 128 * 128;          // 16384 B per [128 x 64] bf16 tile
constexpr int BUFB  = 6 * TILEB;          // a0,a1,a2,w0,w1,w2 : 98304 B
constexpr int SM_BIAS = 2 * BUFB;         // 196608
constexpr int SM_GO   = SM_BIAS + 2048;
constexpr int SM_BO   = SM_GO + 2048;
constexpr int SM_S1   = SM_BO + 2048;
constexpr int SM_S2   = SM_S1 + 512;
constexpr int SM_TOTAL = SM_S2 + 512;     // 203776 B

constexpr int TM = 128;

// ============================ scratch ============================
__device__ __align__(256) float  g_h[98304ull * 512];        // fp32 h / z
__device__ float2 g_stats[98304];
__device__ __align__(256) __nv_bfloat16 g_a0[98304ull * 768];
__device__ __align__(256) __nv_bfloat16 g_a1[98304ull * 768];
__device__ __align__(256) __nv_bfloat16 g_a2[98304ull * 768];
__device__ __align__(256) __nv_bfloat16 g_b0[98304ull * 128];
__device__ __align__(256) __nv_bfloat16 g_b1[98304ull * 128];
__device__ __align__(256) __nv_bfloat16 g_b2[98304ull * 128];
__device__ __align__(256) __nv_bfloat16 g_w0[724992];
__device__ __align__(256) __nv_bfloat16 g_w1[724992];
__device__ __align__(256) __nv_bfloat16 g_w2[724992];
__device__ float g_psum[64 * 32];
__device__ float g_pcnt[64];

// ============================ 3-way split ============================
__device__ __forceinline__ void split3(float a, __nv_bfloat16& h0,
                                       __nv_bfloat16& h1, __nv_bfloat16& h2) {
    h0 = __float2bfloat16_rn(a);
    float r = a - __bfloat162float(h0);
    h1 = __float2bfloat16_rn(r);
    float r2 = r - __bfloat162float(h1);
    h2 = __float2bfloat16_rn(r2);
}
__device__ __forceinline__ uint32_t pack2(__nv_bfloat16 a, __nv_bfloat16 b) {
    return ((uint32_t)__bfloat16_as_ushort(b) << 16) |
           (uint32_t)__bfloat16_as_ushort(a);
}

// ============================ W prep ============================
__global__ void split_w_kernel(const float* __restrict__ W, int off, int n) {
    int i = blockIdx.x * 256 + threadIdx.x;
    if (i < n) {
        __nv_bfloat16 h0, h1, h2;
        split3(W[i], h0, h1, h2);
        g_w0[off + i] = h0;
        g_w1[off + i] = h1;
        g_w2[off + i] = h2;
    }
}

// ============================ activation convert ============================
// optional LN+ReLU, then 3-way split to bf16 planes. 8 elems per thread.
template <bool NORM>
__global__ __launch_bounds__(256) void convert_kernel(
    const float*  __restrict__ h, const float2* __restrict__ stats,
    const float*  __restrict__ g, const float*  __restrict__ be,
    __nv_bfloat16* __restrict__ o0, __nv_bfloat16* __restrict__ o1,
    __nv_bfloat16* __restrict__ o2, int din, int total8) {
    int i = blockIdx.x * 256 + threadIdx.x;
    if (i >= total8) return;
    int cols8 = din >> 3;
    int r = i / cols8;
    int q = i - r * cols8;
    const float* src = h + (int64_t)r * din + q * 8;
    float4 v0 = *(const float4*)src;
    float4 v1 = *(const float4*)(src + 4);
    float x[8] = {v0.x, v0.y, v0.z, v0.w, v1.x, v1.y, v1.z, v1.w};
    if (NORM) {
        float2 st = stats[r];
#pragma unroll
        for (int j = 0; j < 8; j++) {
            int c = q * 8 + j;
            x[j] = fmaxf((x[j] - st.x) * st.y * __ldg(&g[c]) + __ldg(&be[c]),
                         0.f);
        }
    }
    __nv_bfloat16 h0[8], h1[8], h2[8];
#pragma unroll
    for (int j = 0; j < 8; j++) split3(x[j], h0[j], h1[j], h2[j]);
    int64_t o = (int64_t)r * din + q * 8;
    *(uint4*)(o0 + o) = make_uint4(pack2(h0[0], h0[1]), pack2(h0[2], h0[3]),
                                   pack2(h0[4], h0[5]), pack2(h0[6], h0[7]));
    *(uint4*)(o1 + o) = make_uint4(pack2(h1[0], h1[1]), pack2(h1[2], h1[3]),
                                   pack2(h1[4], h1[5]), pack2(h1[6], h1[7]));
    *(uint4*)(o2 + o) = make_uint4(pack2(h2[0], h2[1]), pack2(h2[2], h2[3]),
                                   pack2(h2[4], h2[5]), pack2(h2[6], h2[7]));
}

// ============================ chunk prefetch ============================
template <int DIN, int NPASS>
__device__ __forceinline__ void issue_chunk(
    uint32_t smb, int buf, int64_t r0, int n0, int k0,
    const __nv_bfloat16* __restrict__ a0, const __nv_bfloat16* __restrict__ a1,
    const __nv_bfloat16* __restrict__ a2, const __nv_bfloat16* w0,
    const __nv_bfloat16* w1, const __nv_bfloat16* w2, int tid) {
    const uint32_t base = smb + buf * BUFB;
    const __nv_bfloat16* ap[3] = {a0, a1, a2};
    const __nv_bfloat16* wp[3] = {w0, w1, w2};
#pragma unroll
    for (int s = 0; s < 3; s++) {
#pragma unroll
        for (int it = 0; it < 4; it++) {          // 128*8/256
            int i = tid + it * 256;
            int r = i >> 3, q = i & 7;
            const void* src = ap[s] + (r0 + r) * (int64_t)DIN + k0 + q * 8;
            uint32_t dst = base + s * TILEB + swz((uint32_t)(r * 128 + q * 16));
            CP_ASYNC16(dst, src);
        }
    }
#pragma unroll
    for (int t = 0; t < 3; t++) {
        constexpr int ITW = NPASS * 8 / 256;      // 4 (128) / 1 (32)
#pragma unroll
        for (int it = 0; it < ITW; it++) {
            int i = tid + it * 256;
            int r = i >> 3, q = i & 7;
            const void* src = wp[t] + (n0 + r) * (int64_t)DIN + k0 + q * 8;
            uint32_t dst = base + (3 + t) * TILEB +
                           swz((uint32_t)(r * 128 + q * 16));
            CP_ASYNC16(dst, src);
        }
    }
}

// ============================ layer kernel ============================
// OMODE: 0 = fp32 out + LN stats; 1 = fused LN+ReLU+split to planes; 2 = fp32
template <int DIN, int DOUT, int OMODE>
__global__ __launch_bounds__(256, 1) void layer_kernel(
    const __nv_bfloat16* __restrict__ a0, const __nv_bfloat16* __restrict__ a1,
    const __nv_bfloat16* __restrict__ a2, int w_off,
    const float* __restrict__ bias,
    const float* __restrict__ go, const float* __restrict__ bo,
    float* __restrict__ outf,
    __nv_bfloat16* __restrict__ o0, __nv_bfloat16* __restrict__ o1,
    __nv_bfloat16* __restrict__ o2,
    float2* __restrict__ stats_out) {
    extern __shared__ char sm[];
    const uint32_t smb = smem_u32(sm);
    const int tid  = threadIdx.x;
    const int lane = tid & 31;
    const int wid  = tid >> 5;
    const int wr   = wid >> 1;
    const int wc   = wid & 1;
    const int64_t r0 = (int64_t)blockIdx.x * TM;

    constexpr int NPASS = (DOUT > 128) ? 128 : DOUT;
    constexpr int NT    = DOUT / NPASS;
    constexpr int WC    = NPASS / 2;
    constexpr int NFRAG = WC / 8;
    constexpr int NCH   = DIN / KCH;
    static_assert(OMODE != 1 || NT == 1, "fused split needs NT==1");

    const int R0  = wr * 32;
    const int C0w = wc * WC;

    const int sub  = lane >> 3;
    const int arow = (sub & 1) * 8 + (lane & 7);
    const int acol = (sub >> 1) * 8;
    const int brow = (sub >> 1) * 8 + (lane & 7);
    const int bcol = (sub & 1) * 8;

    float* bias_s = (float*)(sm + SM_BIAS);
    float* go_s   = (float*)(sm + SM_GO);
    float* bo_s   = (float*)(sm + SM_BO);
    float* s1_s   = (float*)(sm + SM_S1);
    float* s2_s   = (float*)(sm + SM_S2);

    for (int i = tid; i < DOUT; i += 256) bias_s[i] = bias[i];
    if (OMODE == 1)
        for (int i = tid; i < DOUT; i += 256) {
            go_s[i] = go[i];
            bo_s[i] = bo[i];
        }
    if (OMODE != 2 && tid < TM) {
        s1_s[tid] = 0.f;
        s2_s[tid] = 0.f;
    }
    __syncthreads();

    const __nv_bfloat16* w0 = g_w0 + w_off;
    const __nv_bfloat16* w1 = g_w1 + w_off;
    const __nv_bfloat16* w2 = g_w2 + w_off;

    float acc[2][NFRAG][4];

    for (int nt = 0; nt < NT; nt++) {
#pragma unroll
        for (int i = 0; i < 2; i++)
#pragma unroll
            for (int j = 0; j < NFRAG; j++)
#pragma unroll
                for (int q = 0; q < 4; q++) acc[i][j][q] = 0.f;

        const int n0 = nt * NPASS;
        issue_chunk<DIN, NPASS>(smb, 0, r0, n0, 0, a0, a1, a2, w0, w1, w2, tid);
        CP_ASYNC_COMMIT();

        for (int ch = 0; ch < NCH; ch++) {
            if (ch + 1 < NCH) {
                issue_chunk<DIN, NPASS>(smb, (ch + 1) & 1, r0, n0,
                                        (ch + 1) * KCH, a0, a1, a2, w0, w1, w2,
                                        tid);
                CP_ASYNC_COMMIT();
                CP_ASYNC_WAIT1();
            } else {
                CP_ASYNC_WAIT0();
            }
            __syncthreads();

            const uint32_t base = smb + (ch & 1) * BUFB;
#pragma unroll
            for (int kk = 0; kk < KCH; kk += 16) {
                uint32_t af[3][2][4];
#pragma unroll
                for (int s = 0; s < 3; s++)
#pragma unroll
                    for (int i = 0; i < 2; i++) {
                        uint32_t off = (uint32_t)((R0 + i * 16 + arow) * 128 +
                                                  (kk + acol) * 2);
                        LDSM4(af[s][i], base + s * TILEB + swz(off));
                    }
#pragma unroll
                for (int j2 = 0; j2 < NFRAG / 2; j2++) {
                    uint32_t bfm[3][4];
#pragma unroll
                    for (int t = 0; t < 3; t++) {
                        uint32_t off = (uint32_t)((C0w + j2 * 16 + brow) * 128 +
                                                  (kk + bcol) * 2);
                        LDSM4(bfm[t], base + (3 + t) * TILEB + swz(off));
                    }
                    constexpr int PS[6] = {2, 0, 1, 1, 0, 0};
                    constexpr int PT[6] = {0, 2, 1, 0, 1, 0};
#pragma unroll
                    for (int p = 0; p < 6; p++) {
                        const int s = PS[p], t = PT[p];
#pragma unroll
                        for (int i = 0; i < 2; i++) {
                            MMA16816(acc[i][2 * j2],     af[s][i],
                                     bfm[t][0], bfm[t][1]);
                            MMA16816(acc[i][2 * j2 + 1], af[s][i],
                                     bfm[t][2], bfm[t][3]);
                        }
                    }
                }
            }
            __syncthreads();   // all warps done with this buffer
        }

        // ---- epilogue: bias in-place, then per-mode output ----
#pragma unroll
        for (int i = 0; i < 2; i++) {
            const int rla = R0 + i * 16 + (lane >> 2);
            float s1a = 0.f, s2a = 0.f, s1b = 0.f, s2b = 0.f;
#pragma unroll
            for (int j = 0; j < NFRAG; j++) {
                int cg = n0 + C0w + j * 8 + (lane & 3) * 2;
                acc[i][j][0] += bias_s[cg];
                acc[i][j][1] += bias_s[cg + 1];
                acc[i][j][2] += bias_s[cg];
                acc[i][j][3] += bias_s[cg + 1];
                if (OMODE != 1) {
                    *(float2*)(outf + (r0 + rla) * (int64_t)DOUT + cg) =
                        make_float2(acc[i][j][0], acc[i][j][1]);
                    *(float2*)(outf + (r0 + rla + 8) * (int64_t)DOUT + cg) =
                        make_float2(acc[i][j][2], acc[i][j][3]);
                }
                if (OMODE != 2) {
                    s1a += acc[i][j][0] + acc[i][j][1];
                    s2a += fmaf(acc[i][j][0], acc[i][j][0],
                                acc[i][j][1] * acc[i][j][1]);
                    s1b += acc[i][j][2] + acc[i][j][3];
                    s2b += fmaf(acc[i][j][2], acc[i][j][2],
                                acc[i][j][3] * acc[i][j][3]);
                }
            }
            if (OMODE != 2) {
#pragma unroll
                for (int o = 1; o <= 2; o <<= 1) {
                    s1a += __shfl_xor_sync(0xffffffffu, s1a, o);
                    s2a += __shfl_xor_sync(0xffffffffu, s2a, o);
                    s1b += __shfl_xor_sync(0xffffffffu, s1b, o);
                    s2b += __shfl_xor_sync(0xffffffffu, s2b, o);
                }
                if ((lane & 3) == 0) {
                    atomicAdd(&s1_s[rla], s1a);
                    atomicAdd(&s2_s[rla], s2a);
                    atomicAdd(&s1_s[rla + 8], s1b);
                    atomicAdd(&s2_s[rla + 8], s2b);
                }
            }
        }
    }

    if (OMODE == 0) {
        __syncthreads();
        if (tid < TM) {
            float mu  = s1_s[tid] * (1.0f / DOUT);
            float var = s2_s[tid] * (1.0f / DOUT) - mu * mu;
            stats_out[r0 + tid] = make_float2(mu, rsqrtf(var + LN_EPS));
        }
    }
    if (OMODE == 1) {
        __syncthreads();
        if (tid < TM) {
            float mu  = s1_s[tid] * (1.0f / DOUT);
            float var = s2_s[tid] * (1.0f / DOUT) - mu * mu;
            s1_s[tid] = mu;
            s2_s[tid] = rsqrtf(var + LN_EPS);
        }
        __syncthreads();
#pragma unroll
        for (int i = 0; i < 2; i++) {
            const int rla = R0 + i * 16 + (lane >> 2);
            float muA = s1_s[rla], rsA = s2_s[rla];
            float muB = s1_s[rla + 8], rsB = s2_s[rla + 8];
#pragma unroll
            for (int j = 0; j < NFRAG; j++) {
                int cg = C0w + j * 8 + (lane & 3) * 2;
                float ga = go_s[cg], gb = go_s[cg + 1];
                float ba = bo_s[cg], bb = bo_s[cg + 1];
                float v0 = fmaxf((acc[i][j][0] - muA) * rsA * ga + ba, 0.f);
                float v1 = fmaxf((acc[i][j][1] - muA) * rsA * gb + bb, 0.f);
                float v2 = fmaxf((acc[i][j][2] - muB) * rsB * ga + ba, 0.f);
                float v3 = fmaxf((acc[i][j][3] - muB) * rsB * gb + bb, 0.f);
                __nv_bfloat16 p0[3], p1[3], p2[3], p3[3];
                split3(v0, p0[0], p0[1], p0[2]);
                split3(v1, p1[0], p1[1], p1[2]);
                split3(v2, p2[0], p2[1], p2[2]);
                split3(v3, p3[0], p3[1], p3[2]);
                int64_t oa = (r0 + rla) * (int64_t)DOUT + cg;
                int64_t ob = (r0 + rla + 8) * (int64_t)DOUT + cg;
                *(uint32_t*)(o0 + oa) = pack2(p0[0], p1[0]);
                *(uint32_t*)(o1 + oa) = pack2(p0[1], p1[1]);
                *(uint32_t*)(o2 + oa) = pack2(p0[2], p1[2]);
                *(uint32_t*)(o0 + ob) = pack2(p2[0], p3[0]);
                *(uint32_t*)(o1 + ob) = pack2(p2[1], p3[1]);
                *(uint32_t*)(o2 + ob) = pack2(p2[2], p3[2]);
            }
        }
    }
}

// ============================ prototypes ============================
__global__ void zero_proto_kernel() {
    int t = blockIdx.x * blockDim.x + threadIdx.x;
    if (t < 64 * 32) g_psum[t] = 0.f;
    if (t < 64) g_pcnt[t] = 0.f;
}

__global__ void proto_accum_kernel(const int* __restrict__ labels,
                                   const float* __restrict__ zs) {
    __shared__ float ssum[64 * 32];
    __shared__ float scnt[64];
    int tid = threadIdx.x, lane = tid & 31, warp = tid >> 5;
    for (int t = tid; t < 64 * 32; t += 256) ssum[t] = 0.f;
    if (tid < 64) scnt[tid] = 0.f;
    __syncthreads();
    int rbase = blockIdx.x * 512;
    for (int r = rbase + warp; r < rbase + 512; r += 8) {
        int lab = labels[r];
        lab = max(0, min(63, lab));
        float v = zs[(size_t)r * 32 + lane];
        atomicAdd(&ssum[lab * 32 + lane], v);
        if (lane == 0) atomicAdd(&scnt[lab], 1.f);
    }
    __syncthreads();
    for (int t = tid; t < 64 * 32; t += 256) atomicAdd(&g_psum[t], ssum[t]);
    if (tid < 64) atomicAdd(&g_pcnt[tid], scnt[tid]);
}

__global__ void proto_finalize_kernel() {
    int tid = threadIdx.x;
    for (int i = tid; i < 64 * 32; i += 256) {
        int c = i >> 5;
        g_psum[i] = g_psum[i] / fmaxf(g_pcnt[c], 1.f);
    }
}

// ============================ -cdist ============================
__global__ __launch_bounds__(256) void dist_kernel(const float* __restrict__ zq,
                                                   float* __restrict__ out) {
    __shared__ float ps[64 * 33];
    __shared__ float pn[64];
    __shared__ float qs[16 * 33];
    int tid = threadIdx.x;
    for (int i = tid; i < 64 * 32; i += 256)
        ps[(i >> 5) * 33 + (i & 31)] = g_psum[i];
    int qbase = blockIdx.x * 16;
    for (int i = tid; i < 16 * 32; i += 256) {
        int q = i >> 5, k = i & 31;
        qs[q * 33 + k] = zq[(size_t)(qbase + q) * 32 + k];
    }
    __syncthreads();
    if (tid < 64) {
        float s = 0.f;
#pragma unroll
        for (int k = 0; k < 32; k++) {
            float v = ps[tid * 33 + k];
            s += v * v;
        }
        pn[tid] = s;
    }
    __syncthreads();
    int c = tid & 63;
#pragma unroll
    for (int p = 0; p < 4; p++) {
        int q = p * 4 + (tid >> 6);
        float dot = 0.f, qn = 0.f;
#pragma unroll
        for (int k = 0; k < 32; k++) {
            float a = qs[q * 33 + k];
            float b = ps[c * 33 + k];
            dot = fmaf(a, b, dot);
            qn  = fmaf(a, a, qn);
        }
        float sq = qn + pn[c] - 2.f * dot;
        out[(size_t)(qbase + q) * 64 + c] = -sqrtf(fmaxf(sq, 0.f));
    }
}

// ============================ launch ============================
extern "C" void kernel_launch(void* const* d_in, const int* in_sizes, int n_in,
                              void* d_out, int out_size) {
    const float* sup = (const float*)d_in[0];
    const int*   lab = (const int*)d_in[1];
    const float* qry = (const float*)d_in[2];
    const float* W1 = (const float*)d_in[3];
    const float* b1 = (const float*)d_in[4];
    const float* g1 = (const float*)d_in[5];
    const float* be1 = (const float*)d_in[6];
    const float* W2 = (const float*)d_in[7];
    const float* b2 = (const float*)d_in[8];
    const float* g2 = (const float*)d_in[9];
    const float* be2 = (const float*)d_in[10];
    const float* W3 = (const float*)d_in[11];
    const float* b3 = (const float*)d_in[12];
    const float* g3 = (const float*)d_in[13];
    const float* be3 = (const float*)d_in[14];
    const float* W4 = (const float*)d_in[15];
    const float* b4 = (const float*)d_in[16];

    cudaFuncSetAttribute(layer_kernel<768, 512, 0>,
                         cudaFuncAttributeMaxDynamicSharedMemorySize, SM_TOTAL);
    cudaFuncSetAttribute(layer_kernel<512, 512, 0>,
                         cudaFuncAttributeMaxDynamicSharedMemorySize, SM_TOTAL);
    cudaFuncSetAttribute(layer_kernel<512, 128, 1>,
                         cudaFuncAttributeMaxDynamicSharedMemorySize, SM_TOTAL);
    cudaFuncSetAttribute(layer_kernel<128, 32, 2>,
                         cudaFuncAttributeMaxDynamicSharedMemorySize, SM_TOTAL);

    float*  h = nullptr;
    float2* st = nullptr;
    __nv_bfloat16 *a0, *a1, *a2, *p0, *p1, *p2;
    cudaGetSymbolAddress((void**)&h, g_h);
    cudaGetSymbolAddress((void**)&st, g_stats);
    cudaGetSymbolAddress((void**)&a0, g_a0);
    cudaGetSymbolAddress((void**)&a1, g_a1);
    cudaGetSymbolAddress((void**)&a2, g_a2);
    cudaGetSymbolAddress((void**)&p0, g_b0);
    cudaGetSymbolAddress((void**)&p1, g_b1);
    cudaGetSymbolAddress((void**)&p2, g_b2);

    // weight pre-split (offsets: 0, 393216, 655360, 720896)
    split_w_kernel<<<(393216 + 255) / 256, 256>>>(W1, 0, 393216);
    split_w_kernel<<<(262144 + 255) / 256, 256>>>(W2, 393216, 262144);
    split_w_kernel<<<(65536 + 255) / 256, 256>>>(W3, 655360, 65536);
    split_w_kernel<<<(4096 + 255) / 256, 256>>>(W4, 720896, 4096);

    // split inputs into bf16 planes (no LN)
    convert_kernel<false><<<(32768 * 96 + 255) / 256, 256>>>(
        sup, nullptr, nullptr, nullptr, a0, a1, a2, 768, 32768 * 96);
    convert_kernel<false><<<(65536 * 96 + 255) / 256, 256>>>(
        qry, nullptr, nullptr, nullptr,
        a0 + (int64_t)32768 * 768, a1 + (int64_t)32768 * 768,
        a2 + (int64_t)32768 * 768, 768, 65536 * 96);

    // L1 : planes(768) -> h fp32 + stats
    layer_kernel<768, 512, 0><<<768, 256, SM_TOTAL>>>(
        a0, a1, a2, 0, b1, nullptr, nullptr, h, nullptr, nullptr, nullptr, st);
    // convert h -> planes(512) with LN1+ReLU
    convert_kernel<true><<<(98304 * 64 + 255) / 256, 256>>>(
        h, st, g1, be1, a0, a1, a2, 512, 98304 * 64);
    // L2
    layer_kernel<512, 512, 0><<<768, 256, SM_TOTAL>>>(
        a0, a1, a2, 393216, b2, nullptr, nullptr, h, nullptr, nullptr, nullptr,
        st);
    convert_kernel<true><<<(98304 * 64 + 255) / 256, 256>>>(
        h, st, g2, be2, a0, a1, a2, 512, 98304 * 64);
    // L3 : fused LN3+ReLU+split -> g_b planes(128)
    layer_kernel<512, 128, 1><<<768, 256, SM_TOTAL>>>(
        a0, a1, a2, 655360, b3, g3, be3, nullptr, p0, p1, p2, nullptr);
    // L4 : planes(128) -> z fp32 (stride 32) into g_h
    layer_kernel<128, 32, 2><<<768, 256, SM_TOTAL>>>(
        p0, p1, p2, 720896, b4, nullptr, nullptr, h, nullptr, nullptr, nullptr,
        nullptr);

    zero_proto_kernel<<<8, 256>>>();
    proto_accum_kernel<<<64, 256>>>(lab, h);
    proto_finalize_kernel<<<1, 256>>>();
    dist_kernel<<<65536 / 16, 256>>>(h + (size_t)32768 * 32, (float*)d_out);
}